// round 4
// baseline (speedup 1.0000x reference)
#include <cuda_runtime.h>

#define FFT_L   8192
#define NLAYERS 4
#define NSTATE  64
#define NROWS   4096
#define THREADS 1024

// ---------------- static device scratch ----------------
__device__ __align__(16) float  g_scratch[(size_t)NROWS * FFT_L];   // 128 MB ping buffer
__device__ __align__(16) float2 g_tw[FFT_L];                        // W_N^k
__device__ __align__(16) float2 g_kraw[NLAYERS][FFT_L];             // raw K(omega_j)
__device__ __align__(16) float2 g_ke[NLAYERS][FFT_L];               // Hermitian kernel * (1/N)

// ---------------- complex helpers ----------------
__device__ __forceinline__ float2 cmul(float2 a, float2 b) {
    return make_float2(fmaf(a.x, b.x, -a.y * b.y), fmaf(a.x, b.y, a.y * b.x));
}
__device__ __forceinline__ float2 cadd(float2 a, float2 b) { return make_float2(a.x + b.x, a.y + b.y); }
__device__ __forceinline__ float2 csub(float2 a, float2 b) { return make_float2(a.x - b.x, a.y - b.y); }
template <bool INV>
__device__ __forceinline__ float2 mulj(float2 a) {   // * (-i) fwd, * (+i) inv
    return INV ? make_float2(-a.y, a.x) : make_float2(a.y, -a.x);
}
__device__ __forceinline__ float gelu_exact(float v) {
    return 0.5f * v * (1.0f + erff(v * 0.70710678118654752f));
}
// bank-conflict-free smem swizzle (bijective, modifies bits 0-3 only)
__device__ __forceinline__ int sw(int i) { return i ^ ((i >> 3) & 15); }

// ---------------- DFT-8 in registers ----------------
template <bool INV>
__device__ __forceinline__ void dft8(float2 a[8]) {
    const float CC = 0.70710678118654752f;
    float2 s0 = cadd(a[0], a[4]), s1 = csub(a[0], a[4]);
    float2 s2 = cadd(a[2], a[6]), s3 = mulj<INV>(csub(a[2], a[6]));
    float2 E0 = cadd(s0, s2), E2 = csub(s0, s2);
    float2 E1 = cadd(s1, s3), E3 = csub(s1, s3);
    float2 t0 = cadd(a[1], a[5]), t1 = csub(a[1], a[5]);
    float2 t2 = cadd(a[3], a[7]), t3 = mulj<INV>(csub(a[3], a[7]));
    float2 O0 = cadd(t0, t2), O2 = csub(t0, t2);
    float2 O1 = cadd(t1, t3), O3 = csub(t1, t3);
    float2 O1w = INV ? make_float2(CC * (O1.x - O1.y), CC * (O1.x + O1.y))
                     : make_float2(CC * (O1.x + O1.y), CC * (O1.y - O1.x));
    float2 O2w = mulj<INV>(O2);
    float2 O3w = INV ? make_float2(-CC * (O3.x + O3.y), CC * (O3.x - O3.y))
                     : make_float2(CC * (O3.y - O3.x), -CC * (O3.x + O3.y));
    a[0] = cadd(E0, O0);  a[4] = csub(E0, O0);
    a[1] = cadd(E1, O1w); a[5] = csub(E1, O1w);
    a[2] = cadd(E2, O2w); a[6] = csub(E2, O2w);
    a[3] = cadd(E3, O3w); a[7] = csub(E3, O3w);
}

// ---------------- prologue kernels ----------------
__global__ void init_tw_kernel() {
    int j = blockIdx.x * blockDim.x + threadIdx.x;
    if (j < FFT_L) {
        float s, c;
        sincospif(-(float)j / (float)(FFT_L / 2), &s, &c);
        g_tw[j] = make_float2(c, s);
    }
}

__global__ void compute_k_kernel(const float* __restrict__ Lr, const float* __restrict__ Li,
                                 const float* __restrict__ P,  const float* __restrict__ B,
                                 const float* __restrict__ Ct, const float* __restrict__ step) {
    int gid = blockIdx.x * blockDim.x + threadIdx.x;
    if (gid >= NLAYERS * FFT_L) return;
    int layer = gid >> 13;
    int j     = gid & (FFT_L - 1);
    const float* lr = Lr + layer * NSTATE;
    const float* li = Li + layer * NSTATE;
    const float* Pp = P  + layer * NSTATE;
    const float* Bp = B  + layer * NSTATE;
    const float* Cp = Ct + layer * NSTATE;
    float st = step[layer];

    float ang = (-6.2831855f * (float)j) / 8192.0f;
    float s, c;
    sincosf(ang, &s, &c);
    float opr = 1.0f + c, opi = s;
    float omr = 1.0f - c, omi = -s;
    float inv_p2 = 1.0f / (opr * opr + opi * opi);
    float qr = (omr * opr + omi * opi) * inv_p2;
    float qi = (omi * opr - omr * opi) * inv_p2;
    float gsc = 2.0f / st;
    float gr = gsc * qr, gi = gsc * qi;
    float cr = 2.0f * opr * inv_p2, ci = -2.0f * opi * inv_p2;

    float k00r = 0.f, k00i = 0.f, k01r = 0.f, k01i = 0.f;
    float k10r = 0.f, k10i = 0.f, k11r = 0.f, k11i = 0.f;
#pragma unroll 8
    for (int n = 0; n < NSTATE; n++) {
        float dr = gr - lr[n];
        float di = gi - li[n];
        float inv = 1.0f / (dr * dr + di * di);
        float ir = dr * inv, ii = -di * inv;
        float b = Bp[n], p = Pp[n], ct = Cp[n];
        float v00 = ct * b, v01 = ct * p, v10 = p * b, v11 = p * p;
        k00r += v00 * ir; k00i += v00 * ii;
        k01r += v01 * ir; k01i += v01 * ii;
        k10r += v10 * ir; k10i += v10 * ii;
        k11r += v11 * ir; k11i += v11 * ii;
    }
    float d1r = 1.0f + k11r, d1i = k11i;
    float invd1 = 1.0f / (d1r * d1r + d1i * d1i);
    float numr = k01r * k10r - k01i * k10i;
    float numi = k01r * k10i + k01i * k10r;
    float qr2 = (numr * d1r + numi * d1i) * invd1;
    float qi2 = (numi * d1r - numr * d1i) * invd1;
    float tr = k00r - qr2, ti = k00i - qi2;
    g_kraw[layer][j] = make_float2(cr * tr - ci * ti, cr * ti + ci * tr);
}

__global__ void symmetrize_k_kernel() {
    int gid = blockIdx.x * blockDim.x + threadIdx.x;
    if (gid >= NLAYERS * FFT_L) return;
    int layer = gid >> 13;
    int j     = gid & (FFT_L - 1);
    float2 K1 = g_kraw[layer][j];
    float2 K2 = g_kraw[layer][(FFT_L - j) & (FFT_L - 1)];
    const float sc = 0.5f / (float)FFT_L;   // Hermitian part * 1/N
    g_ke[layer][j] = make_float2((K1.x + K2.x) * sc, (K1.y - K2.y) * sc);
}

// ---------------- radix-8 pass (1024 butterflies, 1 per thread) ----------------
template <bool INV, int T>
__device__ __forceinline__ void r8_pass(const float2* __restrict__ src,
                                        float2* __restrict__ dst) {
    int idx = threadIdx.x;               // 0..1023
    float2 a[8];
#pragma unroll
    for (int j = 0; j < 8; ++j) a[j] = src[sw(idx + 1024 * j)];
    dft8<INV>(a);
    int pT = idx & ~((1 << T) - 1);      // (idx >> T) << T
    int q  = idx & ((1 << T) - 1);
    float2 w1 = g_tw[pT];
    if (INV) w1.y = -w1.y;
    float2 w2 = cmul(w1, w1), w3 = cmul(w2, w1), w4 = cmul(w2, w2);
    float2 w5 = cmul(w4, w1), w6 = cmul(w3, w3), w7 = cmul(w4, w3);
    int dbase = q + (pT << 3);
    dst[sw(dbase + (0 << T))] = a[0];
    dst[sw(dbase + (1 << T))] = cmul(a[1], w1);
    dst[sw(dbase + (2 << T))] = cmul(a[2], w2);
    dst[sw(dbase + (3 << T))] = cmul(a[3], w3);
    dst[sw(dbase + (4 << T))] = cmul(a[4], w4);
    dst[sw(dbase + (5 << T))] = cmul(a[5], w5);
    dst[sw(dbase + (6 << T))] = cmul(a[6], w6);
    dst[sw(dbase + (7 << T))] = cmul(a[7], w7);
}

// ---------------- fused per-layer kernel ----------------
__global__ void __launch_bounds__(THREADS, 1)
ssm_layer_kernel(const float* __restrict__ in, float* __restrict__ out, int layer) {
    extern __shared__ float2 smem[];
    float2* X = smem;              // swizzled work buffer A
    float2* Y = smem + FFT_L;      // swizzled work buffer B
    float2* U = smem + 2 * FFT_L;  // plain residual stash

    size_t row = (size_t)blockIdx.x * 2;
    const float* in0 = in + row * FFT_L;
    const float* in1 = in + (row + 1) * FFT_L;

    // ---- F1: radix-8 (T=0) reading straight from gmem; stash residual ----
    {
        int idx = threadIdx.x;
        float2 a[8];
#pragma unroll
        for (int j = 0; j < 8; ++j) {
            int i = idx + 1024 * j;
            float2 v = make_float2(in0[i], in1[i]);   // pack 2 real rows as complex
            U[i] = v;
            a[j] = v;
        }
        dft8<false>(a);
        float2 w1 = g_tw[idx];
        float2 w2 = cmul(w1, w1), w3 = cmul(w2, w1), w4 = cmul(w2, w2);
        float2 w5 = cmul(w4, w1), w6 = cmul(w3, w3), w7 = cmul(w4, w3);
        int dbase = idx << 3;
        X[sw(dbase + 0)] = a[0];
        X[sw(dbase + 1)] = cmul(a[1], w1);
        X[sw(dbase + 2)] = cmul(a[2], w2);
        X[sw(dbase + 3)] = cmul(a[3], w3);
        X[sw(dbase + 4)] = cmul(a[4], w4);
        X[sw(dbase + 5)] = cmul(a[5], w5);
        X[sw(dbase + 6)] = cmul(a[6], w6);
        X[sw(dbase + 7)] = cmul(a[7], w7);
    }
    __syncthreads();

    r8_pass<false, 3>(X, Y); __syncthreads();
    r8_pass<false, 6>(Y, X); __syncthreads();
    r8_pass<false, 9>(X, Y); __syncthreads();

    // ---- forward radix-2 tail with the filter fused into the store ----
    {
        const float2* __restrict__ ke = g_ke[layer];
#pragma unroll
        for (int it = 0; it < 4096 / THREADS; ++it) {
            int q = threadIdx.x + it * THREADS;
            float2 a = Y[sw(q)], b = Y[sw(q + 4096)];
            X[sw(q)]        = cmul(cadd(a, b), ke[q]);
            X[sw(q + 4096)] = cmul(csub(a, b), ke[q + 4096]);
        }
    }
    __syncthreads();

    // ---- inverse FFT ----
    r8_pass<true, 0>(X, Y); __syncthreads();
    r8_pass<true, 3>(Y, X); __syncthreads();
    r8_pass<true, 6>(X, Y); __syncthreads();
    r8_pass<true, 9>(Y, X); __syncthreads();

    // ---- inverse radix-2 tail + residual + GELU, straight to gmem ----
    {
        float* o0 = out + row * FFT_L;
        float* o1 = out + (row + 1) * FFT_L;
#pragma unroll
        for (int it = 0; it < 4096 / THREADS; ++it) {
            int q = threadIdx.x + it * THREADS;
            float2 a = X[sw(q)], b = X[sw(q + 4096)];
            float2 lo = cadd(a, b);
            float2 hi = csub(a, b);
            float2 u0 = U[q];
            float2 u1 = U[q + 4096];
            o0[q]        = gelu_exact(lo.x + u0.x);
            o1[q]        = gelu_exact(lo.y + u0.y);
            o0[q + 4096] = gelu_exact(hi.x + u1.x);
            o1[q + 4096] = gelu_exact(hi.y + u1.y);
        }
    }
}

// ---------------- launch ----------------
extern "C" void kernel_launch(void* const* d_in, const int* in_sizes, int n_in,
                              void* d_out, int out_size) {
    const float* u  = (const float*)d_in[0];
    const float* Lr = (const float*)d_in[1];
    const float* Li = (const float*)d_in[2];
    const float* P  = (const float*)d_in[3];
    const float* B  = (const float*)d_in[4];
    const float* Ct = (const float*)d_in[5];
    const float* st = (const float*)d_in[6];
    float* out = (float*)d_out;

    float* scratch = nullptr;
    cudaGetSymbolAddress((void**)&scratch, g_scratch);

    const size_t smem_bytes = 3 * FFT_L * sizeof(float2);   // 192 KB
    cudaFuncSetAttribute(ssm_layer_kernel,
                         cudaFuncAttributeMaxDynamicSharedMemorySize, (int)smem_bytes);

    init_tw_kernel<<<FFT_L / 256, 256>>>();
    compute_k_kernel<<<(NLAYERS * FFT_L) / 256, 256>>>(Lr, Li, P, B, Ct, st);
    symmetrize_k_kernel<<<(NLAYERS * FFT_L) / 256, 256>>>();

    ssm_layer_kernel<<<NROWS / 2, THREADS, smem_bytes>>>(u,       scratch, 0);
    ssm_layer_kernel<<<NROWS / 2, THREADS, smem_bytes>>>(scratch, out,     1);
    ssm_layer_kernel<<<NROWS / 2, THREADS, smem_bytes>>>(out,     scratch, 2);
    ssm_layer_kernel<<<NROWS / 2, THREADS, smem_bytes>>>(scratch, out,     3);
}

// round 5
// speedup vs baseline: 1.1722x; 1.1722x over previous
#include <cuda_runtime.h>

#define FFT_L   8192
#define NLAYERS 4
#define NSTATE  64
#define NROWS   4096
#define THREADS 512

// ---------------- static device scratch ----------------
__device__ __align__(16) float  g_scratch[(size_t)NROWS * FFT_L];   // ping buffer
__device__ __align__(16) float2 g_tw[FFT_L];                        // W_N^k
__device__ __align__(16) float2 g_kraw[NLAYERS][FFT_L];             // raw K(omega_j)
__device__ __align__(16) float2 g_ke[NLAYERS][FFT_L];               // Hermitian kernel * (1/N)

// ---------------- complex helpers ----------------
__device__ __forceinline__ float2 cmul(float2 a, float2 b) {
    return make_float2(fmaf(a.x, b.x, -a.y * b.y), fmaf(a.x, b.y, a.y * b.x));
}
__device__ __forceinline__ float2 cadd(float2 a, float2 b) { return make_float2(a.x + b.x, a.y + b.y); }
__device__ __forceinline__ float2 csub(float2 a, float2 b) { return make_float2(a.x - b.x, a.y - b.y); }
template <bool INV>
__device__ __forceinline__ float2 mulj(float2 a) {   // * (-i) fwd, * (+i) inv
    return INV ? make_float2(-a.y, a.x) : make_float2(a.y, -a.x);
}
__device__ __forceinline__ float gelu_exact(float v) {
    return 0.5f * v * (1.0f + erff(v * 0.70710678118654752f));
}
// pair-level bank swizzle: P indexes 16B pairs (elements 2P, 2P+1)
__device__ __forceinline__ int swp(int P) { return P ^ ((P >> 3) & 7); }
// element access into a pair-swizzled buffer (float2 view)
__device__ __forceinline__ float2 ld_elem(const float2* s, int i) {
    return s[(swp(i >> 1) << 1) | (i & 1)];
}
__device__ __forceinline__ void st_elem(float2* s, int i, float2 v) {
    s[(swp(i >> 1) << 1) | (i & 1)] = v;
}
__device__ __forceinline__ float4 pack2(float2 a, float2 b) {
    return make_float4(a.x, a.y, b.x, b.y);
}

// ---------------- DFT-8 / DFT-16 in registers ----------------
template <bool INV>
__device__ __forceinline__ void dft8(float2 a[8]) {
    const float CC = 0.70710678118654752f;
    float2 s0 = cadd(a[0], a[4]), s1 = csub(a[0], a[4]);
    float2 s2 = cadd(a[2], a[6]), s3 = mulj<INV>(csub(a[2], a[6]));
    float2 E0 = cadd(s0, s2), E2 = csub(s0, s2);
    float2 E1 = cadd(s1, s3), E3 = csub(s1, s3);
    float2 t0 = cadd(a[1], a[5]), t1 = csub(a[1], a[5]);
    float2 t2 = cadd(a[3], a[7]), t3 = mulj<INV>(csub(a[3], a[7]));
    float2 O0 = cadd(t0, t2), O2 = csub(t0, t2);
    float2 O1 = cadd(t1, t3), O3 = csub(t1, t3);
    float2 O1w = INV ? make_float2(CC * (O1.x - O1.y), CC * (O1.x + O1.y))
                     : make_float2(CC * (O1.x + O1.y), CC * (O1.y - O1.x));
    float2 O2w = mulj<INV>(O2);
    float2 O3w = INV ? make_float2(-CC * (O3.x + O3.y), CC * (O3.x - O3.y))
                     : make_float2(CC * (O3.y - O3.x), -CC * (O3.x + O3.y));
    a[0] = cadd(E0, O0);  a[4] = csub(E0, O0);
    a[1] = cadd(E1, O1w); a[5] = csub(E1, O1w);
    a[2] = cadd(E2, O2w); a[6] = csub(E2, O2w);
    a[3] = cadd(E3, O3w); a[7] = csub(E3, O3w);
}

template <bool INV>
__device__ __forceinline__ void dft16(const float2 a[16], float2 X[16]) {
    float2 E[8] = {a[0], a[2], a[4], a[6], a[8], a[10], a[12], a[14]};
    float2 O[8] = {a[1], a[3], a[5], a[7], a[9], a[11], a[13], a[15]};
    dft8<INV>(E);
    dft8<INV>(O);
    const float c1 = 0.9238795325112867f, s1 = 0.3826834323650898f,
                SQ = 0.7071067811865476f;
    const float sg = INV ? 1.0f : -1.0f;
    float2 W[8];
    W[0] = make_float2(1.f, 0.f);
    W[1] = make_float2(c1, sg * s1);
    W[2] = make_float2(SQ, sg * SQ);
    W[3] = make_float2(s1, sg * c1);
    W[4] = make_float2(0.f, sg);
    W[5] = make_float2(-s1, sg * c1);
    W[6] = make_float2(-SQ, sg * SQ);
    W[7] = make_float2(-c1, sg * s1);
#pragma unroll
    for (int k = 0; k < 8; ++k) {
        float2 t = cmul(O[k], W[k]);
        X[k]     = cadd(E[k], t);
        X[k + 8] = csub(E[k], t);
    }
}

// ---------------- prologue kernels ----------------
__global__ void init_tw_kernel() {
    int j = blockIdx.x * blockDim.x + threadIdx.x;
    if (j < FFT_L) {
        float s, c;
        sincospif(-(float)j / (float)(FFT_L / 2), &s, &c);
        g_tw[j] = make_float2(c, s);
    }
}

__global__ void compute_k_kernel(const float* __restrict__ Lr, const float* __restrict__ Li,
                                 const float* __restrict__ P,  const float* __restrict__ B,
                                 const float* __restrict__ Ct, const float* __restrict__ step) {
    int gid = blockIdx.x * blockDim.x + threadIdx.x;
    if (gid >= NLAYERS * FFT_L) return;
    int layer = gid >> 13;
    int j     = gid & (FFT_L - 1);
    const float* lr = Lr + layer * NSTATE;
    const float* li = Li + layer * NSTATE;
    const float* Pp = P  + layer * NSTATE;
    const float* Bp = B  + layer * NSTATE;
    const float* Cp = Ct + layer * NSTATE;
    float st = step[layer];

    float ang = (-6.2831855f * (float)j) / 8192.0f;
    float s, c;
    sincosf(ang, &s, &c);
    float opr = 1.0f + c, opi = s;
    float omr = 1.0f - c, omi = -s;
    float inv_p2 = 1.0f / (opr * opr + opi * opi);
    float qr = (omr * opr + omi * opi) * inv_p2;
    float qi = (omi * opr - omr * opi) * inv_p2;
    float gsc = 2.0f / st;
    float gr = gsc * qr, gi = gsc * qi;
    float cr = 2.0f * opr * inv_p2, ci = -2.0f * opi * inv_p2;

    float k00r = 0.f, k00i = 0.f, k01r = 0.f, k01i = 0.f;
    float k10r = 0.f, k10i = 0.f, k11r = 0.f, k11i = 0.f;
#pragma unroll 8
    for (int n = 0; n < NSTATE; n++) {
        float dr = gr - lr[n];
        float di = gi - li[n];
        float inv = 1.0f / (dr * dr + di * di);
        float ir = dr * inv, ii = -di * inv;
        float b = Bp[n], p = Pp[n], ct = Cp[n];
        float v00 = ct * b, v01 = ct * p, v10 = p * b, v11 = p * p;
        k00r += v00 * ir; k00i += v00 * ii;
        k01r += v01 * ir; k01i += v01 * ii;
        k10r += v10 * ir; k10i += v10 * ii;
        k11r += v11 * ir; k11i += v11 * ii;
    }
    float d1r = 1.0f + k11r, d1i = k11i;
    float invd1 = 1.0f / (d1r * d1r + d1i * d1i);
    float numr = k01r * k10r - k01i * k10i;
    float numi = k01r * k10i + k01i * k10r;
    float qr2 = (numr * d1r + numi * d1i) * invd1;
    float qi2 = (numi * d1r - numr * d1i) * invd1;
    float tr = k00r - qr2, ti = k00i - qi2;
    g_kraw[layer][j] = make_float2(cr * tr - ci * ti, cr * ti + ci * tr);
}

__global__ void symmetrize_k_kernel() {
    int gid = blockIdx.x * blockDim.x + threadIdx.x;
    if (gid >= NLAYERS * FFT_L) return;
    int layer = gid >> 13;
    int j     = gid & (FFT_L - 1);
    float2 K1 = g_kraw[layer][j];
    float2 K2 = g_kraw[layer][(FFT_L - j) & (FFT_L - 1)];
    const float sc = 0.5f / (float)FFT_L;   // Hermitian part * 1/N
    g_ke[layer][j] = make_float2((K1.x + K2.x) * sc, (K1.y - K2.y) * sc);
}

// ---------------- T=0 twiddle+store (per-butterfly chains), pairs within butterfly ----------------
template <bool INV>
__device__ __forceinline__ void store0(float4* __restrict__ dst, float2 a[8], float2 b[8], int t) {
    float4 w01 = *(const float4*)&g_tw[t << 1];
    float2 wA1 = make_float2(w01.x, INV ? -w01.y : w01.y);
    float2 wB1 = make_float2(w01.z, INV ? -w01.w : w01.w);
    float2 wA2 = cmul(wA1, wA1), wA3 = cmul(wA2, wA1), wA4 = cmul(wA2, wA2);
    float2 wA5 = cmul(wA4, wA1), wA6 = cmul(wA3, wA3), wA7 = cmul(wA4, wA3);
    float2 wB2 = cmul(wB1, wB1), wB3 = cmul(wB2, wB1), wB4 = cmul(wB2, wB2);
    float2 wB5 = cmul(wB4, wB1), wB6 = cmul(wB3, wB3), wB7 = cmul(wB4, wB3);
    int Pb = t << 3;
    dst[swp(Pb + 0)] = pack2(a[0],            cmul(a[1], wA1));
    dst[swp(Pb + 1)] = pack2(cmul(a[2], wA2), cmul(a[3], wA3));
    dst[swp(Pb + 2)] = pack2(cmul(a[4], wA4), cmul(a[5], wA5));
    dst[swp(Pb + 3)] = pack2(cmul(a[6], wA6), cmul(a[7], wA7));
    dst[swp(Pb + 4)] = pack2(b[0],            cmul(b[1], wB1));
    dst[swp(Pb + 5)] = pack2(cmul(b[2], wB2), cmul(b[3], wB3));
    dst[swp(Pb + 6)] = pack2(cmul(b[4], wB4), cmul(b[5], wB5));
    dst[swp(Pb + 7)] = pack2(cmul(b[6], wB6), cmul(b[7], wB7));
}

// ---------------- generic radix-8 pass for T in {3, 6}: shared twiddle chain ----------------
template <bool INV, int T>
__device__ __forceinline__ void r8_pass(const float4* __restrict__ src,
                                        float4* __restrict__ dst) {
    int t = threadIdx.x;
    float2 a[8], b[8];
#pragma unroll
    for (int j = 0; j < 8; ++j) {
        float4 v = src[swp(t + 512 * j)];
        a[j] = make_float2(v.x, v.y);
        b[j] = make_float2(v.z, v.w);
    }
    dft8<INV>(a);
    dft8<INV>(b);
    int idx = t << 1;
    int pT = idx & ~((1 << T) - 1);
    int qA = idx & ((1 << T) - 1);
    float2 w1 = g_tw[pT];
    if (INV) w1.y = -w1.y;
    float2 w2 = cmul(w1, w1), w3 = cmul(w2, w1), w4 = cmul(w2, w2);
    float2 w5 = cmul(w4, w1), w6 = cmul(w3, w3), w7 = cmul(w4, w3);
    int Pb = (qA >> 1) + (pT << 2);
    const int S = 1 << (T - 1);
    dst[swp(Pb + 0 * S)] = pack2(a[0], b[0]);
    dst[swp(Pb + 1 * S)] = pack2(cmul(a[1], w1), cmul(b[1], w1));
    dst[swp(Pb + 2 * S)] = pack2(cmul(a[2], w2), cmul(b[2], w2));
    dst[swp(Pb + 3 * S)] = pack2(cmul(a[3], w3), cmul(b[3], w3));
    dst[swp(Pb + 4 * S)] = pack2(cmul(a[4], w4), cmul(b[4], w4));
    dst[swp(Pb + 5 * S)] = pack2(cmul(a[5], w5), cmul(b[5], w5));
    dst[swp(Pb + 6 * S)] = pack2(cmul(a[6], w6), cmul(b[6], w6));
    dst[swp(Pb + 7 * S)] = pack2(cmul(a[7], w7), cmul(b[7], w7));
}

// ---------------- fused per-layer kernel ----------------
__global__ void __launch_bounds__(THREADS, 1)
ssm_layer_kernel(const float* __restrict__ in, float* __restrict__ out, int layer) {
    extern __shared__ float4 smem4[];
    float4* X4 = smem4;             // 4096 pairs, swizzled
    float4* Y4 = smem4 + 4096;      // 4096 pairs, swizzled
    float4* U4 = smem4 + 8192;      // residual stash, plain pair layout

    size_t row = (size_t)blockIdx.x * 2;
    const float* in0 = in + row * FFT_L;
    const float* in1 = in + (row + 1) * FFT_L;
    int t = threadIdx.x;

    // ---- F1: radix-8 (T=0) from gmem; stash residual pairs ----
    {
        float2 a[8], b[8];
#pragma unroll
        for (int j = 0; j < 8; ++j) {
            int i = (t << 1) + 1024 * j;
            float2 va = *(const float2*)(in0 + i);   // (in0[i], in0[i+1])
            float2 vb = *(const float2*)(in1 + i);
            a[j] = make_float2(va.x, vb.x);
            b[j] = make_float2(va.y, vb.y);
            U4[t + 512 * j] = make_float4(va.x, vb.x, va.y, vb.y);
        }
        dft8<false>(a);
        dft8<false>(b);
        store0<false>(X4, a, b, t);
    }
    __syncthreads();

    r8_pass<false, 3>(X4, Y4); __syncthreads();
    r8_pass<false, 6>(Y4, X4); __syncthreads();

    // ---- F4: final radix-16 in registers, filter fused into store ----
    {
        const float2* Xs = (const float2*)X4;
        float2*       Ys = (float2*)Y4;
        const float2* __restrict__ ke = g_ke[layer];
        float2 a[16], Xo[16];
#pragma unroll
        for (int j = 0; j < 16; ++j) a[j] = ld_elem(Xs, t + (j << 9));
        dft16<false>(a, Xo);
#pragma unroll
        for (int k = 0; k < 16; ++k) {
            int i = t + (k << 9);
            st_elem(Ys, i, cmul(Xo[k], ke[i]));
        }
    }
    __syncthreads();

    // ---- inverse FFT ----
    {   // I1: radix-8 (T=0) from smem pairs
        float2 a[8], b[8];
#pragma unroll
        for (int j = 0; j < 8; ++j) {
            float4 v = Y4[swp(t + 512 * j)];
            a[j] = make_float2(v.x, v.y);
            b[j] = make_float2(v.z, v.w);
        }
        dft8<true>(a);
        dft8<true>(b);
        store0<true>(X4, a, b, t);
    }
    __syncthreads();

    r8_pass<true, 3>(X4, Y4); __syncthreads();
    r8_pass<true, 6>(Y4, X4); __syncthreads();

    // ---- I4: final radix-16 + residual + GELU, straight to gmem ----
    {
        const float2* Xs = (const float2*)X4;
        const float2* Ue = (const float2*)U4;   // plain layout: element i at [i]
        float* o0 = out + row * FFT_L;
        float* o1 = out + (row + 1) * FFT_L;
        float2 a[16], Xo[16];
#pragma unroll
        for (int j = 0; j < 16; ++j) a[j] = ld_elem(Xs, t + (j << 9));
        dft16<true>(a, Xo);
#pragma unroll
        for (int k = 0; k < 16; ++k) {
            int i = t + (k << 9);
            float2 u = Ue[i];
            o0[i] = gelu_exact(Xo[k].x + u.x);
            o1[i] = gelu_exact(Xo[k].y + u.y);
        }
    }
}

// ---------------- launch ----------------
extern "C" void kernel_launch(void* const* d_in, const int* in_sizes, int n_in,
                              void* d_out, int out_size) {
    const float* u  = (const float*)d_in[0];
    const float* Lr = (const float*)d_in[1];
    const float* Li = (const float*)d_in[2];
    const float* P  = (const float*)d_in[3];
    const float* B  = (const float*)d_in[4];
    const float* Ct = (const float*)d_in[5];
    const float* st = (const float*)d_in[6];
    float* out = (float*)d_out;

    float* scratch = nullptr;
    cudaGetSymbolAddress((void**)&scratch, g_scratch);

    const size_t smem_bytes = 3 * 4096 * sizeof(float4);   // 192 KB
    cudaFuncSetAttribute(ssm_layer_kernel,
                         cudaFuncAttributeMaxDynamicSharedMemorySize, (int)smem_bytes);

    init_tw_kernel<<<FFT_L / 256, 256>>>();
    compute_k_kernel<<<(NLAYERS * FFT_L) / 256, 256>>>(Lr, Li, P, B, Ct, st);
    symmetrize_k_kernel<<<(NLAYERS * FFT_L) / 256, 256>>>();

    ssm_layer_kernel<<<NROWS / 2, THREADS, smem_bytes>>>(u,       scratch, 0);
    ssm_layer_kernel<<<NROWS / 2, THREADS, smem_bytes>>>(scratch, out,     1);
    ssm_layer_kernel<<<NROWS / 2, THREADS, smem_bytes>>>(out,     scratch, 2);
    ssm_layer_kernel<<<NROWS / 2, THREADS, smem_bytes>>>(scratch, out,     3);
}